// round 6
// baseline (speedup 1.0000x reference)
#include <cuda_runtime.h>

// Problem constants
constexpr int kB  = 32;
constexpr int kC  = 512;
constexpr int kN  = 4096;   // H*W = 64*64
constexpr int kE  = 1024;
constexpr int kNH = 16;

// Output layout: concat of (values[512,1024], pos[512,2], batch[512],
//                           attention[32,4096,16], penalty[1])
constexpr size_t OFF_VAL   = 0;
constexpr size_t OFF_POS   = (size_t)kB * kNH * kE;              // 524288
constexpr size_t OFF_BATCH = OFF_POS + (size_t)kB * kNH * 2;     // 525312
constexpr size_t OFF_ATT   = OFF_BATCH + (size_t)kB * kNH;       // 525824
constexpr size_t OFF_PEN   = OFF_ATT + (size_t)kB * kN * kNH;    // 2622976

constexpr float kNorm   = 0.017683882565766149f;  // 1/(2*pi*9)
constexpr float kInv2S2 = 1.0f / 18.0f;           // 1/(2*sigma^2)

// Scratch (device globals — no allocation allowed)
__device__ float g_xmean[kB * kC];
__device__ float g_pos[kB * 2 * kNH];
__device__ float g_pen[kB * kNH];
__device__ float g_spart[2][kB * kNH * kC]; // n-split partials of s[bh][c]

// ---------------------------------------------------------------------------
// Kernel 1: x_mean[b,c] = mean_n x[b,c,n].  One block per (b,c) row.
// ---------------------------------------------------------------------------
__global__ __launch_bounds__(128) void k_mean(const float* __restrict__ x) {
    const int bc = blockIdx.x;  // 0..16383
    const float4* __restrict__ row = (const float4*)(x + (size_t)bc * kN);
    float s = 0.f;
#pragma unroll
    for (int i = 0; i < 8; i++) {
        float4 v = row[threadIdx.x + i * 128];
        s += (v.x + v.y) + (v.z + v.w);
    }
#pragma unroll
    for (int o = 16; o; o >>= 1) s += __shfl_down_sync(~0u, s, o);
    __shared__ float ws[4];
    if ((threadIdx.x & 31) == 0) ws[threadIdx.x >> 5] = s;
    __syncthreads();
    if (threadIdx.x == 0)
        g_xmean[bc] = ((ws[0] + ws[1]) + (ws[2] + ws[3])) * (1.0f / kN);
}

// ---------------------------------------------------------------------------
// Kernel 2: MLP head.  One block per batch, 1024 threads.
//   hid = silu(x_mean @ w1^T + b1); pos = 31*sigmoid(hid @ w2^T + b2)
// Also writes pos_out and batch outputs.
// ---------------------------------------------------------------------------
__global__ __launch_bounds__(1024) void k_mlp(const float* __restrict__ w1,
                                              const float* __restrict__ b1,
                                              const float* __restrict__ w2,
                                              const float* __restrict__ b2,
                                              float* __restrict__ out) {
    const int b = blockIdx.x;
    const int tid = threadIdx.x;
    __shared__ float xm[kC];
    __shared__ float hid[kE];
    if (tid < kC) xm[tid] = g_xmean[b * kC + tid];
    __syncthreads();

    // hid[tid] over 512-dot
    const float4* __restrict__ wrow = (const float4*)(w1 + (size_t)tid * kC);
    float acc = 0.f;
#pragma unroll 8
    for (int c4 = 0; c4 < kC / 4; c4++) {
        float4 w = wrow[c4];
        acc += w.x * xm[c4 * 4 + 0] + w.y * xm[c4 * 4 + 1] +
               w.z * xm[c4 * 4 + 2] + w.w * xm[c4 * 4 + 3];
    }
    acc += b1[tid];
    hid[tid] = acc / (1.0f + expf(-acc));   // silu
    __syncthreads();

    // pos: warp k computes output k (k = 0..31), 1024-dot with shuffle reduce
    const int k = tid >> 5, lane = tid & 31;
    float a = 0.f;
#pragma unroll 8
    for (int i = lane; i < kE; i += 32) a += hid[i] * w2[k * kE + i];
#pragma unroll
    for (int o = 16; o; o >>= 1) a += __shfl_down_sync(~0u, a, o);
    if (lane == 0) {
        float p = 31.0f / (1.0f + expf(-(a + b2[k])));
        g_pos[b * 32 + k] = p;
        out[OFF_POS + b * 32 + k] = p;
    }
    if (tid < kNH) out[OFF_BATCH + b * kNH + tid] = (float)b;
}

// ---------------------------------------------------------------------------
// Kernel 3: attention[b,n,h] = norm*exp(-0.5*||grid[n]-pos[b,h]||^2 / s^2)
// Writes the attention output only. Grid: (chunk=16, b=32), 256 threads.
// ---------------------------------------------------------------------------
__global__ __launch_bounds__(256) void k_attn(float* __restrict__ out) {
    const int chunk = blockIdx.x, b = blockIdx.y;
    const int tid = threadIdx.x;
    __shared__ float ps[32];
    if (tid < 32) ps[tid] = g_pos[b * 32 + tid];
    __syncthreads();

    const int n = chunk * 256 + tid;
    const float fi = (float)(n >> 6);
    const float fj = (float)(n & 63);
    float av[16];
#pragma unroll
    for (int h = 0; h < 16; h++) {
        float dx = fi - ps[2 * h];
        float dy = fj - ps[2 * h + 1];
        av[h] = kNorm * expf(-(dx * dx + dy * dy) * kInv2S2);
    }
    float4* __restrict__ dst =
        (float4*)(out + OFF_ATT + (((size_t)b * kN + n) << 4));
    dst[0] = make_float4(av[0], av[1], av[2], av[3]);
    dst[1] = make_float4(av[4], av[5], av[6], av[7]);
    dst[2] = make_float4(av[8], av[9], av[10], av[11]);
    dst[3] = make_float4(av[12], av[13], av[14], av[15]);
}

// ---------------------------------------------------------------------------
// Kernel 3b: pen[b,h] — XLA-GPU column-reduction order:
//   lane y accumulates att[b, y+32k, h] for k = 0..127 sequentially (fp32),
//   then the 32 lane-partials combine via shfl_down tree (16,8,4,2,1).
// One warp per (b,h). Grid: 32 blocks (b), 512 threads (16 warps = 16 h).
// ---------------------------------------------------------------------------
__global__ __launch_bounds__(512) void k_pen(const float* __restrict__ att) {
    const int b = blockIdx.x;
    const int h = threadIdx.x >> 5;   // warp id = head
    const int y = threadIdx.x & 31;   // lane
    const float* __restrict__ p = att + (size_t)b * kN * kNH + h;
    float acc = 0.f;
#pragma unroll 4
    for (int k = 0; k < kN / 32; k++)
        acc = __fadd_rn(acc, p[(size_t)(y + 32 * k) * kNH]);
#pragma unroll
    for (int o = 16; o; o >>= 1)
        acc = __fadd_rn(acc, __shfl_down_sync(~0u, acc, o));
    if (y == 0) g_pen[b * kNH + h] = acc;
}

// ---------------------------------------------------------------------------
// Kernel 3c: penalty = mean over 512 of (pen-1)^2.  The terms are all
// positive and of similar magnitude, so the sum is order-insensitive at the
// 1e-7 relative level; fp64 sequential is fine. Single thread.
// ---------------------------------------------------------------------------
__global__ void k_penalty(float* __restrict__ out) {
    double s = 0.0;
    for (int i = 0; i < kB * kNH; i++) {
        float d = __fadd_rn(g_pen[i], -1.0f);
        s += (double)__fmul_rn(d, d);
    }
    out[OFF_PEN] = (float)(s * (1.0 / 512.0));
}

// ---------------------------------------------------------------------------
// Kernel 5: s[b,h,c] = sum_n attn[b,n,h] * x[b,c,n]   (the hot kernel)
// Grid: (ctile=4, nsplit=2, b=32), 128 threads. Thread owns one c and
// accumulates 16 h as 8 packed float2 via Blackwell fma.rn.f32x2.
// Attention staged in SMEM in 64-n chunks (broadcast reads).
// ---------------------------------------------------------------------------
__global__ __launch_bounds__(128) void k_s(const float* __restrict__ x,
                                           const float* __restrict__ att) {
    const int tid = threadIdx.x;
    const int ctile = blockIdx.x, ns = blockIdx.y, b = blockIdx.z;
    const int c = ctile * 128 + tid;

    __shared__ float4 satt4[256];  // 64 n-rows x 16 h = 1024 floats
    const unsigned long long* s2 = (const unsigned long long*)satt4;

    const float4* __restrict__ xrow =
        (const float4*)(x + (size_t)(b * kC + c) * kN + (size_t)ns * 2048);
    const float4* __restrict__ arow =
        (const float4*)(att + ((size_t)b * kN + (size_t)ns * 2048) * kNH);

    unsigned long long acc[8];
#pragma unroll
    for (int k = 0; k < 8; k++) acc[k] = 0ull;

    for (int nc = 0; nc < 32; nc++) {  // 32 chunks of 64 n
        satt4[tid]       = arow[nc * 256 + tid];
        satt4[tid + 128] = arow[nc * 256 + tid + 128];
        __syncthreads();
#pragma unroll 4
        for (int d4 = 0; d4 < 16; d4++) {
            float4 xv = xrow[nc * 16 + d4];
#pragma unroll
            for (int e = 0; e < 4; e++) {
                float xs = (e == 0) ? xv.x : (e == 1) ? xv.y : (e == 2) ? xv.z : xv.w;
                unsigned long long xp;
                asm("mov.b64 %0, {%1, %1};" : "=l"(xp) : "f"(xs));
                const unsigned long long* row = s2 + (d4 * 4 + e) * 8;
#pragma unroll
                for (int k = 0; k < 8; k++) {
                    asm("fma.rn.f32x2 %0, %1, %2, %0;"
                        : "+l"(acc[k])
                        : "l"(row[k]), "l"(xp));
                }
            }
        }
        __syncthreads();
    }
#pragma unroll
    for (int k = 0; k < 8; k++) {
        float lo, hi;
        asm("mov.b64 {%0, %1}, %2;" : "=f"(lo), "=f"(hi) : "l"(acc[k]));
        g_spart[ns][(b * kNH + 2 * k) * kC + c]     = lo;
        g_spart[ns][(b * kNH + 2 * k + 1) * kC + c] = hi;
    }
}

// ---------------------------------------------------------------------------
// Kernel 6: values[bh, e] = sum_c s[bh,c]*wv[e,c] + bv[e]*pen[bh]
// Tiled SMEM GEMM: BM=64 (bh), BN=64 (e), BK=32, 256 threads, 4x4 micro-tile.
// ---------------------------------------------------------------------------
__global__ __launch_bounds__(256) void k_values(const float* __restrict__ wv,
                                                const float* __restrict__ bv,
                                                float* __restrict__ out) {
    const int ntile = blockIdx.x;  // 0..15 (e)
    const int mtile = blockIdx.y;  // 0..7  (bh)
    const int tid = threadIdx.x;
    const int tx = tid & 15, ty = tid >> 4;
    const int bm0 = mtile * 64, bn0 = ntile * 64;

    __shared__ float sA[32][68];  // [k][m], pad keeps float4-aligned rows
    __shared__ float sB[32][68];  // [k][n]
    float acc[4][4] = {};

    for (int k0 = 0; k0 < kC; k0 += 32) {
#pragma unroll
        for (int r = 0; r < 2; r++) {
            const int f = tid * 2 + r;   // 0..511
            const int m = f >> 3, kq = f & 7;
            const float4* p0 =
                (const float4*)(&g_spart[0][(size_t)(bm0 + m) * kC + k0]) + kq;
            const float4* p1 =
                (const float4*)(&g_spart[1][(size_t)(bm0 + m) * kC + k0]) + kq;
            float4 v0 = *p0, v1 = *p1;
            sA[kq * 4 + 0][m] = v0.x + v1.x;
            sA[kq * 4 + 1][m] = v0.y + v1.y;
            sA[kq * 4 + 2][m] = v0.z + v1.z;
            sA[kq * 4 + 3][m] = v0.w + v1.w;
            const float4* q =
                (const float4*)(wv + (size_t)(bn0 + m) * kC + k0) + kq;
            float4 w = *q;
            sB[kq * 4 + 0][m] = w.x;
            sB[kq * 4 + 1][m] = w.y;
            sB[kq * 4 + 2][m] = w.z;
            sB[kq * 4 + 3][m] = w.w;
        }
        __syncthreads();
#pragma unroll
        for (int k = 0; k < 32; k++) {
            float4 a = *(const float4*)&sA[k][ty * 4];
            float4 bq = *(const float4*)&sB[k][tx * 4];
            float av[4] = {a.x, a.y, a.z, a.w};
            float bvv[4] = {bq.x, bq.y, bq.z, bq.w};
#pragma unroll
            for (int i = 0; i < 4; i++)
#pragma unroll
                for (int j = 0; j < 4; j++) acc[i][j] += av[i] * bvv[j];
        }
        __syncthreads();
    }

#pragma unroll
    for (int i = 0; i < 4; i++) {
        const int bh = bm0 + ty * 4 + i;
        const float pv = g_pen[bh];
        const int e = bn0 + tx * 4;
        float4 o;
        o.x = acc[i][0] + bv[e + 0] * pv;
        o.y = acc[i][1] + bv[e + 1] * pv;
        o.z = acc[i][2] + bv[e + 2] * pv;
        o.w = acc[i][3] + bv[e + 3] * pv;
        *(float4*)(out + OFF_VAL + (size_t)bh * kE + e) = o;
    }
}

// ---------------------------------------------------------------------------
extern "C" void kernel_launch(void* const* d_in, const int* in_sizes, int n_in,
                              void* d_out, int out_size) {
    (void)in_sizes; (void)n_in; (void)out_size;
    const float* x  = (const float*)d_in[0];
    const float* w1 = (const float*)d_in[1];
    const float* b1 = (const float*)d_in[2];
    const float* w2 = (const float*)d_in[3];
    const float* b2 = (const float*)d_in[4];
    const float* wv = (const float*)d_in[5];
    const float* bv = (const float*)d_in[6];
    float* out = (float*)d_out;

    k_mean<<<kB * kC, 128>>>(x);
    k_mlp<<<kB, 1024>>>(w1, b1, w2, b2, out);
    k_attn<<<dim3(16, kB), 256>>>(out);
    k_pen<<<kB, 512>>>(out + OFF_ATT);
    k_penalty<<<1, 1>>>(out);
    k_s<<<dim3(4, 2, kB), 128>>>(x, out + OFF_ATT);
    k_values<<<dim3(16, 8), 256>>>(wv, bv, out);
}

// round 9
// speedup vs baseline: 1.2382x; 1.2382x over previous
#include <cuda_runtime.h>

// Problem constants
constexpr int kB  = 32;
constexpr int kC  = 512;
constexpr int kN  = 4096;   // H*W = 64*64
constexpr int kE  = 1024;
constexpr int kNH = 16;
constexpr int kNS = 4;      // n-splits for k_s

// Output layout: concat of (values[512,1024], pos[512,2], batch[512],
//                           attention[32,4096,16], penalty[1])
constexpr size_t OFF_VAL   = 0;
constexpr size_t OFF_POS   = (size_t)kB * kNH * kE;              // 524288
constexpr size_t OFF_BATCH = OFF_POS + (size_t)kB * kNH * 2;     // 525312
constexpr size_t OFF_ATT   = OFF_BATCH + (size_t)kB * kNH;       // 525824
constexpr size_t OFF_PEN   = OFF_ATT + (size_t)kB * kN * kNH;    // 2622976

constexpr float kNorm   = 0.017683882565766149f;  // 1/(2*pi*9)
constexpr float kInv2S2 = 1.0f / 18.0f;           // 1/(2*sigma^2)

// Scratch (device globals — no allocation allowed)
__device__ float g_xmean[kB * kC];
__device__ float g_pos[kB * 2 * kNH];
__device__ float g_pen[kB * kNH];
__device__ float g_att_t[kB][kNH][kN];        // transposed attention (8MB)
__device__ float g_spart[kNS][kB * kNH * kC]; // n-split partials of s[bh][c]

// ---------------------------------------------------------------------------
// Kernel 1: x_mean[b,c] = mean_n x[b,c,n].  One block per (b,c) row.
// ---------------------------------------------------------------------------
__global__ __launch_bounds__(128) void k_mean(const float* __restrict__ x) {
    const int bc = blockIdx.x;  // 0..16383
    const float4* __restrict__ row = (const float4*)(x + (size_t)bc * kN);
    float s = 0.f;
#pragma unroll
    for (int i = 0; i < 8; i++) {
        float4 v = row[threadIdx.x + i * 128];
        s += (v.x + v.y) + (v.z + v.w);
    }
#pragma unroll
    for (int o = 16; o; o >>= 1) s += __shfl_down_sync(~0u, s, o);
    __shared__ float ws[4];
    if ((threadIdx.x & 31) == 0) ws[threadIdx.x >> 5] = s;
    __syncthreads();
    if (threadIdx.x == 0)
        g_xmean[bc] = ((ws[0] + ws[1]) + (ws[2] + ws[3])) * (1.0f / kN);
}

// ---------------------------------------------------------------------------
// Kernel 2: MLP head.  One block per batch, 1024 threads.
// ---------------------------------------------------------------------------
__global__ __launch_bounds__(1024) void k_mlp(const float* __restrict__ w1,
                                              const float* __restrict__ b1,
                                              const float* __restrict__ w2,
                                              const float* __restrict__ b2,
                                              float* __restrict__ out) {
    const int b = blockIdx.x;
    const int tid = threadIdx.x;
    __shared__ float xm[kC];
    __shared__ float hid[kE];
    if (tid < kC) xm[tid] = g_xmean[b * kC + tid];
    __syncthreads();

    const float4* __restrict__ wrow = (const float4*)(w1 + (size_t)tid * kC);
    float acc = 0.f;
#pragma unroll 8
    for (int c4 = 0; c4 < kC / 4; c4++) {
        float4 w = wrow[c4];
        acc += w.x * xm[c4 * 4 + 0] + w.y * xm[c4 * 4 + 1] +
               w.z * xm[c4 * 4 + 2] + w.w * xm[c4 * 4 + 3];
    }
    acc += b1[tid];
    hid[tid] = acc / (1.0f + expf(-acc));   // silu
    __syncthreads();

    const int k = tid >> 5, lane = tid & 31;
    float a = 0.f;
#pragma unroll 8
    for (int i = lane; i < kE; i += 32) a += hid[i] * w2[k * kE + i];
#pragma unroll
    for (int o = 16; o; o >>= 1) a += __shfl_down_sync(~0u, a, o);
    if (lane == 0) {
        float p = 31.0f / (1.0f + expf(-(a + b2[k])));
        g_pos[b * 32 + k] = p;
        out[OFF_POS + b * 32 + k] = p;
    }
    if (tid < kNH) out[OFF_BATCH + b * kNH + tid] = (float)b;
}

// ---------------------------------------------------------------------------
// Kernel 3: attention[b,n,h].  Writes the [n][h] output AND a transposed
// [h][n] copy (coalesced: consecutive tid -> consecutive n).
// Grid: (chunk=16, b=32), 256 threads.
// ---------------------------------------------------------------------------
__global__ __launch_bounds__(256) void k_attn(float* __restrict__ out) {
    const int chunk = blockIdx.x, b = blockIdx.y;
    const int tid = threadIdx.x;
    __shared__ float ps[32];
    if (tid < 32) ps[tid] = g_pos[b * 32 + tid];
    __syncthreads();

    const int n = chunk * 256 + tid;
    const float fi = (float)(n >> 6);
    const float fj = (float)(n & 63);
    float av[16];
#pragma unroll
    for (int h = 0; h < 16; h++) {
        float dx = fi - ps[2 * h];
        float dy = fj - ps[2 * h + 1];
        av[h] = kNorm * expf(-(dx * dx + dy * dy) * kInv2S2);
    }
    float4* __restrict__ dst =
        (float4*)(out + OFF_ATT + (((size_t)b * kN + n) << 4));
    dst[0] = make_float4(av[0], av[1], av[2], av[3]);
    dst[1] = make_float4(av[4], av[5], av[6], av[7]);
    dst[2] = make_float4(av[8], av[9], av[10], av[11]);
    dst[3] = make_float4(av[12], av[13], av[14], av[15]);
#pragma unroll
    for (int h = 0; h < 16; h++) g_att_t[b][h][n] = av[h];
}

// ---------------------------------------------------------------------------
// Kernel 3b: pen[b,h] — same values, same order as R6 (lane y sums n=y+32k
// ascending, then shfl_down tree) but reading the coalesced transposed copy.
// Bit-identical result, ~6x less memory traffic waste.
// ---------------------------------------------------------------------------
__global__ __launch_bounds__(512) void k_pen() {
    const int b = blockIdx.x;
    const int h = threadIdx.x >> 5;   // warp id = head
    const int y = threadIdx.x & 31;   // lane
    const float* __restrict__ p = g_att_t[b][h];
    float acc = 0.f;
#pragma unroll 4
    for (int k = 0; k < kN / 32; k++)
        acc = __fadd_rn(acc, p[y + 32 * k]);
#pragma unroll
    for (int o = 16; o; o >>= 1)
        acc = __fadd_rn(acc, __shfl_down_sync(~0u, acc, o));
    if (y == 0) g_pen[b * kNH + h] = acc;
}

// ---------------------------------------------------------------------------
// Kernel 3c: penalty = mean over 512 of (pen-1)^2.
// ---------------------------------------------------------------------------
__global__ void k_penalty(float* __restrict__ out) {
    double s = 0.0;
    for (int i = 0; i < kB * kNH; i++) {
        float d = __fadd_rn(g_pen[i], -1.0f);
        s += (double)__fmul_rn(d, d);
    }
    out[OFF_PEN] = (float)(s * (1.0 / 512.0));
}

// ---------------------------------------------------------------------------
// Kernel 5: s[b,h,c] = sum_n attn[b,n,h] * x[b,c,n]   (the hot kernel)
// Grid: (ctile=4, ns=4, b=32) = 512 blocks, 128 threads.
// Per 64-n chunk: x tile [128c x 64n] staged into SMEM with COALESCED global
// loads (16 threads per row segment); att chunk [64n x 16h] staged as before.
// Thread owns one c, accumulates 16 h as 8 packed f32x2; xs pad 65 makes the
// compute-phase xs[tid][n] reads bank-conflict-free.
// ---------------------------------------------------------------------------
__global__ __launch_bounds__(128) void k_s(const float* __restrict__ x,
                                           const float* __restrict__ att) {
    const int tid = threadIdx.x;
    const int ctile = blockIdx.x, ns = blockIdx.y, b = blockIdx.z;
    const int n0 = ns * (kN / kNS);       // 1024-wide n slab

    __shared__ float xs[128][65];         // [c][n] + pad
    __shared__ float4 satt4[256];         // 64 n-rows x 16 h
    const unsigned long long* s2 = (const unsigned long long*)satt4;

    const float4* __restrict__ arow =
        (const float4*)(att + ((size_t)b * kN + n0) * kNH);
    const int lr = tid >> 4, lc4 = tid & 15;   // staging: row-half, col float4
    const float* __restrict__ xbase =
        x + (size_t)(b * kC + ctile * 128) * kN + n0;

    unsigned long long acc[8];
#pragma unroll
    for (int k = 0; k < 8; k++) acc[k] = 0ull;

    for (int nc = 0; nc < 16; nc++) {     // 16 chunks of 64 n
        satt4[tid]       = arow[nc * 256 + tid];
        satt4[tid + 128] = arow[nc * 256 + tid + 128];
#pragma unroll
        for (int r8 = 0; r8 < 16; r8++) {
            const int row = r8 * 8 + lr;
            float4 v = *(const float4*)(xbase + (size_t)row * kN + nc * 64 + lc4 * 4);
            xs[row][lc4 * 4 + 0] = v.x;
            xs[row][lc4 * 4 + 1] = v.y;
            xs[row][lc4 * 4 + 2] = v.z;
            xs[row][lc4 * 4 + 3] = v.w;
        }
        __syncthreads();
#pragma unroll 8
        for (int n = 0; n < 64; n++) {
            const float xv = xs[tid][n];
            unsigned long long xp;
            asm("mov.b64 %0, {%1, %1};" : "=l"(xp) : "f"(xv));
            const unsigned long long* row = s2 + n * 8;
#pragma unroll
            for (int k = 0; k < 8; k++) {
                asm("fma.rn.f32x2 %0, %1, %2, %0;"
                    : "+l"(acc[k])
                    : "l"(row[k]), "l"(xp));
            }
        }
        __syncthreads();
    }
    const int c = ctile * 128 + tid;
#pragma unroll
    for (int k = 0; k < 8; k++) {
        float lo, hi;
        asm("mov.b64 {%0, %1}, %2;" : "=f"(lo), "=f"(hi) : "l"(acc[k]));
        g_spart[ns][(b * kNH + 2 * k) * kC + c]     = lo;
        g_spart[ns][(b * kNH + 2 * k + 1) * kC + c] = hi;
    }
}

// ---------------------------------------------------------------------------
// Kernel 6: values[bh, e] = sum_c s[bh,c]*wv[e,c] + bv[e]*pen[bh]
// Tiled SMEM GEMM: BM=64 (bh), BN=64 (e), BK=32, 256 threads, 4x4 micro-tile.
// ---------------------------------------------------------------------------
__global__ __launch_bounds__(256) void k_values(const float* __restrict__ wv,
                                                const float* __restrict__ bv,
                                                float* __restrict__ out) {
    const int ntile = blockIdx.x;  // 0..15 (e)
    const int mtile = blockIdx.y;  // 0..7  (bh)
    const int tid = threadIdx.x;
    const int tx = tid & 15, ty = tid >> 4;
    const int bm0 = mtile * 64, bn0 = ntile * 64;

    __shared__ float sA[32][68];  // [k][m]
    __shared__ float sB[32][68];  // [k][n]
    float acc[4][4] = {};

    for (int k0 = 0; k0 < kC; k0 += 32) {
#pragma unroll
        for (int r = 0; r < 2; r++) {
            const int f = tid * 2 + r;   // 0..511
            const int m = f >> 3, kq = f & 7;
            float4 vs = make_float4(0.f, 0.f, 0.f, 0.f);
#pragma unroll
            for (int p = 0; p < kNS; p++) {
                const float4 v =
                    *((const float4*)(&g_spart[p][(size_t)(bm0 + m) * kC + k0]) + kq);
                vs.x += v.x; vs.y += v.y; vs.z += v.z; vs.w += v.w;
            }
            sA[kq * 4 + 0][m] = vs.x;
            sA[kq * 4 + 1][m] = vs.y;
            sA[kq * 4 + 2][m] = vs.z;
            sA[kq * 4 + 3][m] = vs.w;
            const float4 w =
                *((const float4*)(wv + (size_t)(bn0 + m) * kC + k0) + kq);
            sB[kq * 4 + 0][m] = w.x;
            sB[kq * 4 + 1][m] = w.y;
            sB[kq * 4 + 2][m] = w.z;
            sB[kq * 4 + 3][m] = w.w;
        }
        __syncthreads();
#pragma unroll
        for (int k = 0; k < 32; k++) {
            float4 a = *(const float4*)&sA[k][ty * 4];
            float4 bq = *(const float4*)&sB[k][tx * 4];
            float av[4] = {a.x, a.y, a.z, a.w};
            float bvv[4] = {bq.x, bq.y, bq.z, bq.w};
#pragma unroll
            for (int i = 0; i < 4; i++)
#pragma unroll
                for (int j = 0; j < 4; j++) acc[i][j] += av[i] * bvv[j];
        }
        __syncthreads();
    }

#pragma unroll
    for (int i = 0; i < 4; i++) {
        const int bh = bm0 + ty * 4 + i;
        const float pv = g_pen[bh];
        const int e = bn0 + tx * 4;
        float4 o;
        o.x = acc[i][0] + bv[e + 0] * pv;
        o.y = acc[i][1] + bv[e + 1] * pv;
        o.z = acc[i][2] + bv[e + 2] * pv;
        o.w = acc[i][3] + bv[e + 3] * pv;
        *(float4*)(out + OFF_VAL + (size_t)bh * kE + e) = o;
    }
}

// ---------------------------------------------------------------------------
extern "C" void kernel_launch(void* const* d_in, const int* in_sizes, int n_in,
                              void* d_out, int out_size) {
    (void)in_sizes; (void)n_in; (void)out_size;
    const float* x  = (const float*)d_in[0];
    const float* w1 = (const float*)d_in[1];
    const float* b1 = (const float*)d_in[2];
    const float* w2 = (const float*)d_in[3];
    const float* b2 = (const float*)d_in[4];
    const float* wv = (const float*)d_in[5];
    const float* bv = (const float*)d_in[6];
    float* out = (float*)d_out;

    k_mean<<<kB * kC, 128>>>(x);
    k_mlp<<<kB, 1024>>>(w1, b1, w2, b2, out);
    k_attn<<<dim3(16, kB), 256>>>(out);
    k_pen<<<kB, 512>>>();
    k_penalty<<<1, 1>>>(out);
    k_s<<<dim3(4, kNS, kB), 128>>>(x, out + OFF_ATT);
    k_values<<<dim3(16, 8), 256>>>(wv, bv, out);
}